// round 6
// baseline (speedup 1.0000x reference)
#include <cuda_runtime.h>
#include <math.h>

#define VOLD   256
#define NGAUSS 4000
// Tile shape 4 x 8 x 16 (x,y,z): 32 (x,y) rows -> 32 lanes; 64B z-row stores.
#define TSX 4
#define TSY 8
#define TSZ 16
#define NTX 64
#define NTY 32
#define NTZ 16
#define NTILES (NTX * NTY * NTZ)      // 32768
#define CAP    32
#define SLICE  28                     // wx[4] wy[8] wz[16]

// ---------------------------------------------------------------------------
// Static device scratch. Zeroed at module load; gather self-cleans g_cnt each
// launch, so the invariant holds across correctness run, capture, and replays.
// ---------------------------------------------------------------------------
__device__ int g_cnt[NTILES];
__device__ __align__(16) float g_slice[(size_t)NTILES * CAP * SLICE];

// ---------------------------------------------------------------------------
// Kernel 1: block per Gaussian (4000 blocks). Threads 0..95 compute the 3x32
// separable weight window (one exp each); then thread-per-tile pair scatter:
// one atomicAdd + 7 float4 slice stores per (gaussian, tile) pair.
// ---------------------------------------------------------------------------
__global__ __launch_bounds__(128) void prep_kernel(
    const float* __restrict__ centers,
    const float* __restrict__ sigmas,
    const float* __restrict__ intens)
{
    const int g = blockIdx.x;
    const int t = threadIdx.x;

    __shared__ float sw[3][32];
    __shared__ int s_tmin[3], s_tn[3], s_start[3];

    const float sig    = sigmas[g];
    const float inv2s2 = 0.5f / (sig * sig);
    const float I      = intens[g];
    const float cut    = 3.0f * sig * 255.0f;

    if (t < 96) {
        const int axis = t >> 5;
        const int o    = t & 31;

        const float cn = centers[3 * g + axis];
        const float cv = cn * 255.0f;

        const float minf = fmaxf(cv - cut, 0.0f);
        const float maxf = fminf(cv + cut, 255.0f);
        const int   mini = (int)floorf(minf);
        const int   maxi = min((int)floorf(maxf) + 1, VOLD);   // exclusive
        const int   start = min(mini, VOLD - 32);

        const int idx = start + o;
        float w = 0.0f;
        if (idx >= mini && idx < maxi) {
            const float d = (float)idx * (1.0f / 255.0f) - cn;
            w = expf(-d * d * inv2s2);
        }
        if (axis == 0) w *= I;
        sw[axis][o] = w;

        if (o == 0) {
            const int sh   = (axis == 0) ? 2 : ((axis == 1) ? 3 : 4);
            const int tmin = mini >> sh;
            const int tmax = (maxi - 1) >> sh;
            s_tmin[axis]  = tmin;
            s_tn[axis]    = tmax - tmin + 1;
            s_start[axis] = start;
        }
    }
    __syncthreads();

    const int x0 = s_tmin[0], y0 = s_tmin[1], z0 = s_tmin[2];
    const int nx = s_tn[0],   ny = s_tn[1],   nz = s_tn[2];
    const int st0 = s_start[0], st1 = s_start[1], st2 = s_start[2];

    const int total = nx * ny * nz;
    for (int i = t; i < total; i += 128) {
        const int iz = i % nz;
        const int r  = i / nz;
        const int iy = r % ny;
        const int ix = r / ny;
        const int tx = x0 + ix, ty = y0 + iy, tz = z0 + iz;
        const int tile = (tx * NTY + ty) * NTZ + tz;

        const int slot = atomicAdd(&g_cnt[tile], 1);
        if (slot < CAP) {
            float* dst = g_slice + ((size_t)tile * CAP + slot) * SLICE;
            const int k0 = (tx << 2) - st0;
            const int k1 = (ty << 3) - st1;
            const int k2 = (tz << 4) - st2;

            float4 v;
            // wx: 4 floats
            v.x = ((unsigned)(k0+0) < 32u) ? sw[0][k0+0] : 0.f;
            v.y = ((unsigned)(k0+1) < 32u) ? sw[0][k0+1] : 0.f;
            v.z = ((unsigned)(k0+2) < 32u) ? sw[0][k0+2] : 0.f;
            v.w = ((unsigned)(k0+3) < 32u) ? sw[0][k0+3] : 0.f;
            *(float4*)(dst + 0) = v;
            // wy: 8 floats
#pragma unroll
            for (int h = 0; h < 2; ++h) {
                const int k = k1 + 4 * h;
                v.x = ((unsigned)(k+0) < 32u) ? sw[1][k+0] : 0.f;
                v.y = ((unsigned)(k+1) < 32u) ? sw[1][k+1] : 0.f;
                v.z = ((unsigned)(k+2) < 32u) ? sw[1][k+2] : 0.f;
                v.w = ((unsigned)(k+3) < 32u) ? sw[1][k+3] : 0.f;
                *(float4*)(dst + 4 + 4 * h) = v;
            }
            // wz: 16 floats
#pragma unroll
            for (int h = 0; h < 4; ++h) {
                const int k = k2 + 4 * h;
                v.x = ((unsigned)(k+0) < 32u) ? sw[2][k+0] : 0.f;
                v.y = ((unsigned)(k+1) < 32u) ? sw[2][k+1] : 0.f;
                v.z = ((unsigned)(k+2) < 32u) ? sw[2][k+2] : 0.f;
                v.w = ((unsigned)(k+3) < 32u) ? sw[2][k+3] : 0.f;
                *(float4*)(dst + 12 + 4 * h) = v;
            }
        }
    }
}

// ---------------------------------------------------------------------------
// Kernel 2: gather, warp per 4x8x16 tile, 8 tiles per 256-thread block.
// Lane = (x,y) row; 16-voxel z row in registers; 4 contiguous float4 stores.
// ---------------------------------------------------------------------------
__global__ __launch_bounds__(256, 5) void gather_kernel(float* __restrict__ vol) {
    const int warp = threadIdx.x >> 5;
    const int lane = threadIdx.x & 31;
    const int tile = blockIdx.x * 8 + warp;

    __shared__ __align__(16) float sh[8][CAP * SLICE];   // 28 KB

    const int cnt = min(g_cnt[tile], CAP);

    // Coalesced warp stage: cnt*7 contiguous float4s
    const float4* __restrict__ src =
        (const float4*)(g_slice + (size_t)tile * CAP * SLICE);
    float4* shv = (float4*)sh[warp];
    for (int i = lane; i < cnt * (SLICE / 4); i += 32) shv[i] = src[i];
    __syncwarp();
    if (lane == 0) g_cnt[tile] = 0;       // restore invariant for next launch

    const int x = lane >> 3;              // 0..3
    const int y = lane & 7;               // 0..7

    float a[16];
#pragma unroll
    for (int i = 0; i < 16; ++i) a[i] = 0.f;

    const float* __restrict__ swp = sh[warp];
#pragma unroll 4
    for (int p = 0; p < cnt; ++p) {
        const float* s = swp + p * SLICE;
        const float f = s[x] * s[4 + y];
#pragma unroll
        for (int q = 0; q < 4; ++q) {
            const float4 wz = *(const float4*)(s + 12 + 4 * q);
            a[4*q+0] = fmaf(f, wz.x, a[4*q+0]);
            a[4*q+1] = fmaf(f, wz.y, a[4*q+1]);
            a[4*q+2] = fmaf(f, wz.z, a[4*q+2]);
            a[4*q+3] = fmaf(f, wz.w, a[4*q+3]);
        }
    }

    const int tzi = tile & (NTZ - 1);
    const int tyi = (tile >> 4) & (NTY - 1);
    const int txi = tile >> 9;
    float* out = vol + ((size_t)(txi * TSX + x) * VOLD + (tyi * TSY + y)) * VOLD
                     + tzi * TSZ;
#pragma unroll
    for (int q = 0; q < 4; ++q)
        *(float4*)(out + 4 * q) = make_float4(a[4*q+0], a[4*q+1], a[4*q+2], a[4*q+3]);
}

// ---------------------------------------------------------------------------
extern "C" void kernel_launch(void* const* d_in, const int* in_sizes, int n_in,
                              void* d_out, int out_size) {
    const float* centers = (const float*)d_in[0];
    const float* sigmas  = (const float*)d_in[1];
    const float* intens  = (const float*)d_in[2];
    float* vol = (float*)d_out;

    prep_kernel<<<NGAUSS, 128>>>(centers, sigmas, intens);
    gather_kernel<<<NTILES / 8, 256>>>(vol);
}